// round 9
// baseline (speedup 1.0000x reference)
#include <cuda_runtime.h>
#include <cuda_bf16.h>
#include <math.h>
#include <stdint.h>

#define HID   1024
#define GATES 4096
#define BB    8
#define TT    256
#define MM    2048
#define VOC   50257

typedef unsigned long long u64;

// ---------------- scratch ----------------
__device__ float g_emb[(size_t)MM * HID];
__device__ float g_xproj[(size_t)MM * GATES];
__device__ float g_hall[(size_t)MM * HID];
__device__ float g_hbuf[2][BB * HID];
__device__ float g_c[BB * HID];
__device__ float g_lse[MM];
__device__ int   g_bar_cnt = 0;
__device__ int   g_bar_gen = 0;

// bf16 split operands
__device__ __nv_bfloat16 g_ebh[(size_t)VOC * HID];
__device__ __nv_bfloat16 g_ebl[(size_t)VOC * HID];
__device__ __nv_bfloat16 g_wh [(size_t)GATES * HID];
__device__ __nv_bfloat16 g_wl [(size_t)GATES * HID];
__device__ __nv_bfloat16 g_rwh[(size_t)GATES * HID];   // w_hh hi
__device__ __nv_bfloat16 g_rwl[(size_t)GATES * HID];   // w_hh lo
__device__ __nv_bfloat16 g_xh [(size_t)MM * HID];
__device__ __nv_bfloat16 g_xl [(size_t)MM * HID];
__device__ __nv_bfloat16 g_hh2[(size_t)MM * HID];
__device__ __nv_bfloat16 g_hl2[(size_t)MM * HID];

// ---------------- helpers ----------------
__device__ __forceinline__ void cpasync16(uint32_t dst, const void* src) {
    asm volatile("cp.async.cg.shared.global [%0], [%1], 16;\n" :: "r"(dst), "l"(src));
}
#define CP_COMMIT() asm volatile("cp.async.commit_group;\n")

__device__ __forceinline__ float fexp(float x) {
    float y = fmaxf(x * 1.4426950408889634f, -120.f);
    float n = rintf(y);
    float f = y - n;
    float p = 0.0013333558f;
    p = fmaf(p, f, 0.0096181291f);
    p = fmaf(p, f, 0.0555041087f);
    p = fmaf(p, f, 0.2402265069f);
    p = fmaf(p, f, 0.6931471806f);
    p = fmaf(p, f, 1.0f);
    return p * __int_as_float(((int)n + 127) << 23);
}

__device__ __forceinline__ void mma16816(float* d, const uint32_t* a, const uint32_t* b) {
    asm volatile(
        "mma.sync.aligned.m16n8k16.row.col.f32.bf16.bf16.f32 "
        "{%0,%1,%2,%3}, {%4,%5,%6,%7}, {%8,%9}, {%0,%1,%2,%3};"
        : "+f"(d[0]), "+f"(d[1]), "+f"(d[2]), "+f"(d[3])
        : "r"(a[0]), "r"(a[1]), "r"(a[2]), "r"(a[3]), "r"(b[0]), "r"(b[1]));
}

// ---------------- small kernels ----------------
__global__ void zero_state_kernel() {
    int i = blockIdx.x * blockDim.x + threadIdx.x;
    if (i < BB * HID) { g_hbuf[0][i] = 0.f; g_c[i] = 0.f; }
}

__global__ void gather_kernel(const int* __restrict__ x, const float* __restrict__ embW) {
    int m = blockIdx.x;
    int t = m >> 3, b = m & 7;
    int tok = x[b * TT + t];
    const float4* src = (const float4*)(embW + (size_t)tok * HID);
    float4* dst = (float4*)(g_emb + (size_t)m * HID);
    dst[threadIdx.x] = src[threadIdx.x];
}

__global__ void split_kernel(const float* __restrict__ s, __nv_bfloat16* __restrict__ h,
                             __nv_bfloat16* __restrict__ l, long n) {
    long i = blockIdx.x * (long)blockDim.x + threadIdx.x;
    long st = (long)gridDim.x * blockDim.x;
    for (; i < n; i += st) {
        float f = s[i];
        __nv_bfloat16 hv = __float2bfloat16(f);
        h[i] = hv;
        l[i] = __float2bfloat16(f - __bfloat162float(hv));
    }
}

// ---------------- mma.sync split-bf16 NT GEMM (from R7, passing) ----------------
#define BKP 40
#define BUF_B (128 * BKP * 2)
#define STAGE_B (4 * BUF_B)
#define MMSMEM (2 * STAGE_B)

__device__ __forceinline__ void stage_chunk_mma(
    char* smem, int stage, int tid, int kc,
    const __nv_bfloat16* Ah, const __nv_bfloat16* Al,
    const __nv_bfloat16* Bh, const __nv_bfloat16* Bl,
    int m0, int n0, int Nrows, int K)
{
    uint32_t sb = (uint32_t)__cvta_generic_to_shared(smem) + (uint32_t)stage * STAGE_B;
    #pragma unroll
    for (int i = 0; i < 8; i++) {
        int u = tid + 256 * i;
        int buf = u >> 9;
        int o = u & 511;
        int row = o >> 2;
        int col = (o & 3) * 8;
        const __nv_bfloat16* src;
        if (buf < 2) {
            src = ((buf == 0) ? Ah : Al) + (size_t)(m0 + row) * K + kc + col;
        } else {
            int n = n0 + row; if (n >= Nrows) n = Nrows - 1;
            src = ((buf == 2) ? Bh : Bl) + (size_t)n * K + kc + col;
        }
        cpasync16(sb + (uint32_t)(buf * BUF_B + (row * BKP + col) * 2), src);
    }
}

__global__ void __launch_bounds__(256)
mm_bf16_kernel(const __nv_bfloat16* __restrict__ Ah, const __nv_bfloat16* __restrict__ Al,
               const __nv_bfloat16* __restrict__ Bh, const __nv_bfloat16* __restrict__ Bl,
               const float* __restrict__ bias1, const float* __restrict__ bias2,
               float* __restrict__ C, int Nrows, int ldc, int K)
{
    extern __shared__ char smem[];
    int tid = threadIdx.x;
    int wid = tid >> 5, lane = tid & 31;
    int m0 = blockIdx.x * 128;
    int n0 = blockIdx.y * 128;
    int m0w = (wid >> 2) * 64;
    int n0w = (wid & 3) * 32;
    const int NC = K / 32;

    float acc[4][4][4];
    #pragma unroll
    for (int mf = 0; mf < 4; mf++)
        #pragma unroll
        for (int nf = 0; nf < 4; nf++)
            #pragma unroll
            for (int e = 0; e < 4; e++) acc[mf][nf][e] = 0.f;

    stage_chunk_mma(smem, 0, tid, 0, Ah, Al, Bh, Bl, m0, n0, Nrows, K);
    CP_COMMIT();
    stage_chunk_mma(smem, 1, tid, 32, Ah, Al, Bh, Bl, m0, n0, Nrows, K);
    CP_COMMIT();

    int ar = lane >> 2;
    int ac = (lane & 3) * 2;

    for (int c = 0; c < NC; c++) {
        if (c < NC - 1) asm volatile("cp.async.wait_group 1;" ::: "memory");
        else            asm volatile("cp.async.wait_group 0;" ::: "memory");
        __syncthreads();

        const __nv_bfloat16* st = (const __nv_bfloat16*)(smem + (c & 1) * STAGE_B);
        const __nv_bfloat16* pAh = st;
        const __nv_bfloat16* pAl = st + 128 * BKP;
        const __nv_bfloat16* pBh = st + 2 * 128 * BKP;
        const __nv_bfloat16* pBl = st + 3 * 128 * BKP;

        #pragma unroll
        for (int ks = 0; ks < 32; ks += 16) {
            uint32_t fAh[4][4], fAl[4][4], fBh[4][2], fBl[4][2];
            #pragma unroll
            for (int mf = 0; mf < 4; mf++) {
                int r = m0w + mf * 16 + ar;
                int cc = ks + ac;
                fAh[mf][0] = *(const uint32_t*)(pAh + r * BKP + cc);
                fAh[mf][1] = *(const uint32_t*)(pAh + (r + 8) * BKP + cc);
                fAh[mf][2] = *(const uint32_t*)(pAh + r * BKP + cc + 8);
                fAh[mf][3] = *(const uint32_t*)(pAh + (r + 8) * BKP + cc + 8);
                fAl[mf][0] = *(const uint32_t*)(pAl + r * BKP + cc);
                fAl[mf][1] = *(const uint32_t*)(pAl + (r + 8) * BKP + cc);
                fAl[mf][2] = *(const uint32_t*)(pAl + r * BKP + cc + 8);
                fAl[mf][3] = *(const uint32_t*)(pAl + (r + 8) * BKP + cc + 8);
            }
            #pragma unroll
            for (int nf = 0; nf < 4; nf++) {
                int n = n0w + nf * 8 + ar;
                int kk = ks + ac;
                fBh[nf][0] = *(const uint32_t*)(pBh + n * BKP + kk);
                fBh[nf][1] = *(const uint32_t*)(pBh + n * BKP + kk + 8);
                fBl[nf][0] = *(const uint32_t*)(pBl + n * BKP + kk);
                fBl[nf][1] = *(const uint32_t*)(pBl + n * BKP + kk + 8);
            }
            #pragma unroll
            for (int mf = 0; mf < 4; mf++)
                #pragma unroll
                for (int nf = 0; nf < 4; nf++) {
                    mma16816(acc[mf][nf], fAh[mf], fBh[nf]);
                    mma16816(acc[mf][nf], fAh[mf], fBl[nf]);
                    mma16816(acc[mf][nf], fAl[mf], fBh[nf]);
                }
        }
        __syncthreads();
        if (c + 2 < NC) {
            stage_chunk_mma(smem, c & 1, tid, (c + 2) * 32, Ah, Al, Bh, Bl, m0, n0, Nrows, K);
            CP_COMMIT();
        }
    }

    // epilogue: scalar stores (ldc may be odd)
    #pragma unroll
    for (int mf = 0; mf < 4; mf++) {
        int row0 = m0 + m0w + mf * 16 + ar;
        float* r0p = C + (size_t)row0 * ldc;
        float* r1p = C + (size_t)(row0 + 8) * ldc;
        #pragma unroll
        for (int nf = 0; nf < 4; nf++) {
            int col = n0 + n0w + nf * 8 + ac;
            #pragma unroll
            for (int e = 0; e < 2; e++) {
                int cc = col + e;
                if (cc < Nrows) {
                    float bv = 0.f;
                    if (bias1) bv += bias1[cc];
                    if (bias2) bv += bias2[cc];
                    r0p[cc] = acc[mf][nf][e] + bv;
                    r1p[cc] = acc[mf][nf][2 + e] + bv;
                }
            }
        }
    }
}

// ---------------- persistent LSTM with mma.sync recurrent GEMM ----------------
#define WPAD 1032                       // bf16 elements per padded row
#define LP_SWH 0
#define LP_SWL 66048
#define LP_SHH 132096
#define LP_SHL 148608
#define LP_RED 165120                   // 2048 floats: [row][b][warp]
#define LP_GATES 173312                 // 256 floats
#define LP_SMEM 174336

__global__ void __launch_bounds__(256)
lstm_persistent_kernel(const __nv_bfloat16* __restrict__ rwh,
                       const __nv_bfloat16* __restrict__ rwl)
{
    extern __shared__ char smraw[];
    __nv_bfloat16* swh = (__nv_bfloat16*)(smraw + LP_SWH);
    __nv_bfloat16* swl = (__nv_bfloat16*)(smraw + LP_SWL);
    __nv_bfloat16* shh = (__nv_bfloat16*)(smraw + LP_SHH);
    __nv_bfloat16* shl = (__nv_bfloat16*)(smraw + LP_SHL);
    float* red      = (float*)(smraw + LP_RED);
    float* sm_gates = (float*)(smraw + LP_GATES);

    int tid = threadIdx.x;
    int jb = blockIdx.x * 8;

    // ---- one-time: stage split weights (32 rows x 1024, hi+lo) ----
    {
        uint32_t sb = (uint32_t)__cvta_generic_to_shared(smraw);
        #pragma unroll
        for (int i = 0; i < 32; i++) {
            int u = tid + 256 * i;          // 0..8191 16B-chunks
            int buf = u >> 12;              // 0:hi 1:lo
            int o = u & 4095;
            int row = o >> 7;               // 0..31 (g*8+jl)
            int ch = o & 127;
            int g = row >> 3, jl = row & 7;
            const __nv_bfloat16* src = (buf ? rwl : rwh)
                + (size_t)(g * HID + jb + jl) * HID + ch * 8;
            cpasync16(sb + (uint32_t)(buf * LP_SWL + row * (WPAD * 2) + ch * 16), src);
        }
        CP_COMMIT();
        asm volatile("cp.async.wait_group 0;\n" ::: "memory");
        __syncthreads();
    }

    int wid = tid >> 5, lane = tid & 31;
    int ar = lane >> 2;                     // 0..7
    int ac = (lane & 3) * 2;                // 0,2,4,6
    int ejl = tid >> 3, eb = tid & 7;       // epilogue mapping (tid<64)
    float c_reg = 0.f;

    for (int t = 0; t < TT; t++) {
        const float* hprev = g_hbuf[t & 1];
        float* hnext = g_hbuf[(t + 1) & 1];

        // ---- stage h: fp32 global -> bf16 hi/lo smem (ALL 2048 float4) ----
        {
            const float4* hp4 = (const float4*)hprev;
            #pragma unroll
            for (int i = 0; i < 8; i++) {
                int f4 = tid + 256 * i;     // 0..2047
                float4 v = __ldcg(hp4 + f4);
                int batch = f4 >> 8;        // 0..7
                int k = (f4 & 255) * 4;
                int off = batch * WPAD + k;
                __nv_bfloat16 h0 = __float2bfloat16(v.x);
                __nv_bfloat16 h1 = __float2bfloat16(v.y);
                __nv_bfloat16 h2 = __float2bfloat16(v.z);
                __nv_bfloat16 h3 = __float2bfloat16(v.w);
                __nv_bfloat16 l0 = __float2bfloat16(v.x - __bfloat162float(h0));
                __nv_bfloat16 l1 = __float2bfloat16(v.y - __bfloat162float(h1));
                __nv_bfloat16 l2 = __float2bfloat16(v.z - __bfloat162float(h2));
                __nv_bfloat16 l3 = __float2bfloat16(v.w - __bfloat162float(h3));
                uint2 ph, pl;
                ph.x = ((uint32_t)__bfloat16_as_ushort(h1) << 16) | __bfloat16_as_ushort(h0);
                ph.y = ((uint32_t)__bfloat16_as_ushort(h3) << 16) | __bfloat16_as_ushort(h2);
                pl.x = ((uint32_t)__bfloat16_as_ushort(l1) << 16) | __bfloat16_as_ushort(l0);
                pl.y = ((uint32_t)__bfloat16_as_ushort(l3) << 16) | __bfloat16_as_ushort(l2);
                *(uint2*)(shh + off) = ph;
                *(uint2*)(shl + off) = pl;
            }
        }
        __syncthreads();

        // ---- recurrent GEMM: warp wid handles k in [wid*128, wid*128+128) ----
        float acc[2][4];
        #pragma unroll
        for (int mt = 0; mt < 2; mt++)
            #pragma unroll
            for (int e = 0; e < 4; e++) acc[mt][e] = 0.f;

        #pragma unroll
        for (int ks8 = 0; ks8 < 8; ks8++) {
            int kk = wid * 128 + ks8 * 16;
            uint32_t bh[2], bl[2];
            bh[0] = *(const uint32_t*)(shh + ar * WPAD + kk + ac);
            bh[1] = *(const uint32_t*)(shh + ar * WPAD + kk + ac + 8);
            bl[0] = *(const uint32_t*)(shl + ar * WPAD + kk + ac);
            bl[1] = *(const uint32_t*)(shl + ar * WPAD + kk + ac + 8);
            #pragma unroll
            for (int mt = 0; mt < 2; mt++) {
                int r = mt * 16 + ar;
                uint32_t ah[4], al[4];
                ah[0] = *(const uint32_t*)(swh + r * WPAD + kk + ac);
                ah[1] = *(const uint32_t*)(swh + (r + 8) * WPAD + kk + ac);
                ah[2] = *(const uint32_t*)(swh + r * WPAD + kk + ac + 8);
                ah[3] = *(const uint32_t*)(swh + (r + 8) * WPAD + kk + ac + 8);
                al[0] = *(const uint32_t*)(swl + r * WPAD + kk + ac);
                al[1] = *(const uint32_t*)(swl + (r + 8) * WPAD + kk + ac);
                al[2] = *(const uint32_t*)(swl + r * WPAD + kk + ac + 8);
                al[3] = *(const uint32_t*)(swl + (r + 8) * WPAD + kk + ac + 8);
                mma16816(acc[mt], ah, bh);
                mma16816(acc[mt], ah, bl);
                mma16816(acc[mt], al, bh);
            }
        }

        // ---- cross-warp k-reduce via smem: red[row*64 + b*8 + wid] ----
        #pragma unroll
        for (int mt = 0; mt < 2; mt++)
            #pragma unroll
            for (int e = 0; e < 4; e++) {
                int row = mt * 16 + ar + ((e & 2) ? 8 : 0);
                int b = ac + (e & 1);
                red[row * 64 + b * 8 + wid] = acc[mt][e];
            }
        __syncthreads();

        {   // thread tid owns (row=tid>>3, b=tid&7); red offset = tid*8
            float4 p0 = *(float4*)(red + tid * 8);
            float4 p1 = *(float4*)(red + tid * 8 + 4);
            int row = tid >> 3, b = tid & 7;
            int g = row >> 3, jl = row & 7;
            sm_gates[tid] = ((p0.x + p0.y) + (p0.z + p0.w))
                          + ((p1.x + p1.y) + (p1.z + p1.w))
                          + g_xproj[((size_t)t * BB + b) * GATES + g * HID + jb + jl];
        }
        __syncthreads();

        if (tid < 64) {
            int j = jb + ejl;
            float gi = sm_gates[(0 * 8 + ejl) * 8 + eb];
            float gf = sm_gates[(1 * 8 + ejl) * 8 + eb];
            float gg = sm_gates[(2 * 8 + ejl) * 8 + eb];
            float go = sm_gates[(3 * 8 + ejl) * 8 + eb];
            gi = 1.f / (1.f + expf(-gi));
            gf = 1.f / (1.f + expf(-gf));
            gg = tanhf(gg);
            go = 1.f / (1.f + expf(-go));
            c_reg = gf * c_reg + gi * gg;
            float h = go * tanhf(c_reg);
            hnext[eb * HID + j] = h;
            g_hall[((size_t)eb * TT + t) * HID + j] = h;
            if (t == TT - 1) g_c[eb * HID + j] = c_reg;
            __threadfence();
        }

        // ---- software grid barrier ----
        __syncthreads();
        if (tid == 0) {
            int gen = *((volatile int*)&g_bar_gen);
            __threadfence();
            if (atomicAdd(&g_bar_cnt, 1) == (int)gridDim.x - 1) {
                g_bar_cnt = 0;
                __threadfence();
                atomicAdd(&g_bar_gen, 1);
            } else {
                while (*((volatile int*)&g_bar_gen) == gen) { }
            }
            __threadfence();
        }
        __syncthreads();
    }
}

// ---------------- log-softmax ----------------
__global__ void __launch_bounds__(256)
row_lse_kernel(const float* __restrict__ logits)
{
    int row = blockIdx.x;
    const float* p = logits + (size_t)row * VOC;
    float m = -1e30f, s = 0.f;
    for (int i = threadIdx.x; i < VOC; i += 256) {
        float v = p[i];
        if (v > m) { s = s * fexp(m - v) + 1.f; m = v; }
        else       { s += fexp(v - m); }
    }
    __shared__ float sm[256], ss[256];
    sm[threadIdx.x] = m; ss[threadIdx.x] = s;
    __syncthreads();
    for (int off = 128; off; off >>= 1) {
        if (threadIdx.x < off) {
            float m1 = sm[threadIdx.x], s1 = ss[threadIdx.x];
            float m2 = sm[threadIdx.x + off], s2 = ss[threadIdx.x + off];
            float mm = fmaxf(m1, m2);
            sm[threadIdx.x] = mm;
            ss[threadIdx.x] = s1 * fexp(m1 - mm) + s2 * fexp(m2 - mm);
        }
        __syncthreads();
    }
    if (threadIdx.x == 0) g_lse[row] = sm[0] + logf(ss[0]);
}

__global__ void __launch_bounds__(256)
sub_lse_kernel(float* __restrict__ out)
{
    int row = blockIdx.x;
    float l = g_lse[row];
    float* p = out + (size_t)row * VOC;
    for (int i = threadIdx.x; i < VOC; i += 256) p[i] -= l;
}

__global__ void write_hidden_kernel(float* __restrict__ out)
{
    int i = blockIdx.x * blockDim.x + threadIdx.x;
    size_t base = (size_t)MM * VOC;
    if (i < BB * HID)               out[base + i] = g_hbuf[0][i];
    else if (i < 2 * BB * HID)      out[base + i] = g_c[i - BB * HID];
}

// ---------------- launcher ----------------
extern "C" void kernel_launch(void* const* d_in, const int* in_sizes, int n_in,
                              void* d_out, int out_size)
{
    const int*   x     = (const int*)  d_in[0];
    const float* emb_W = (const float*)d_in[1];
    const float* w_ih  = (const float*)d_in[2];
    const float* w_hh  = (const float*)d_in[3];
    const float* b_ih  = (const float*)d_in[4];
    const float* b_hh  = (const float*)d_in[5];
    const float* dec_b = (const float*)d_in[6];
    float* out = (float*)d_out;

    float* emb_p;   cudaGetSymbolAddress((void**)&emb_p,   g_emb);
    float* xproj_p; cudaGetSymbolAddress((void**)&xproj_p, g_xproj);
    float* hall_p;  cudaGetSymbolAddress((void**)&hall_p,  g_hall);
    __nv_bfloat16 *ebh, *ebl, *wh, *wl, *rwh, *rwl, *xh, *xl, *hh2, *hl2;
    cudaGetSymbolAddress((void**)&ebh, g_ebh);
    cudaGetSymbolAddress((void**)&ebl, g_ebl);
    cudaGetSymbolAddress((void**)&wh,  g_wh);
    cudaGetSymbolAddress((void**)&wl,  g_wl);
    cudaGetSymbolAddress((void**)&rwh, g_rwh);
    cudaGetSymbolAddress((void**)&rwl, g_rwl);
    cudaGetSymbolAddress((void**)&xh,  g_xh);
    cudaGetSymbolAddress((void**)&xl,  g_xl);
    cudaGetSymbolAddress((void**)&hh2, g_hh2);
    cudaGetSymbolAddress((void**)&hl2, g_hl2);

    cudaFuncSetAttribute(lstm_persistent_kernel,
                         cudaFuncAttributeMaxDynamicSharedMemorySize, LP_SMEM);
    cudaFuncSetAttribute(mm_bf16_kernel,
                         cudaFuncAttributeMaxDynamicSharedMemorySize, MMSMEM);

    zero_state_kernel<<<(BB * HID + 255) / 256, 256>>>();
    gather_kernel<<<MM, 256>>>(x, emb_W);

    split_kernel<<<4096, 256>>>(emb_W, ebh, ebl, (long)VOC * HID);
    split_kernel<<<1024, 256>>>(w_ih,  wh,  wl,  (long)GATES * HID);
    split_kernel<<<1024, 256>>>(w_hh,  rwh, rwl, (long)GATES * HID);
    split_kernel<<<512,  256>>>(emb_p, xh,  xl,  (long)MM * HID);

    // x_proj = emb @ w_ih^T + (b_ih + b_hh)
    {
        dim3 grid(MM / 128, GATES / 128);
        mm_bf16_kernel<<<grid, 256, MMSMEM>>>(xh, xl, wh, wl, b_ih, b_hh,
                                              xproj_p, GATES, GATES, HID);
    }

    // all 256 LSTM steps: persistent, tensor-core recurrent GEMM
    lstm_persistent_kernel<<<HID / 8, 256, LP_SMEM>>>(rwh, rwl);

    split_kernel<<<512, 256>>>(hall_p, hh2, hl2, (long)MM * HID);

    // decoder: logits = h_all @ emb_W^T + dec_b
    {
        dim3 grid(MM / 128, (VOC + 127) / 128);
        mm_bf16_kernel<<<grid, 256, MMSMEM>>>(hh2, hl2, ebh, ebl, dec_b,
                                              (const float*)0, out, VOC, VOC, HID);
    }

    row_lse_kernel<<<MM, 256>>>(out);
    sub_lse_kernel<<<MM, 256>>>(out);

    if (out_size >= MM * VOC + 2 * BB * HID)
        write_hidden_kernel<<<(2 * BB * HID + 255) / 256, 256>>>(out);
}

// round 10
// speedup vs baseline: 1.0169x; 1.0169x over previous
#include <cuda_runtime.h>
#include <cuda_bf16.h>
#include <math.h>
#include <stdint.h>

#define HID   1024
#define GATES 4096
#define BB    8
#define TT    256
#define MM    2048
#define VOC   50257

typedef unsigned long long u64;

// ---------------- scratch ----------------
__device__ float g_xproj[(size_t)MM * GATES];
__device__ float g_hbuf[2][BB * HID];
__device__ float g_c[BB * HID];
__device__ float g_lse[MM];
__device__ int   g_bar_flags[128 * 32];     // one flag per CTA, 128B apart
__device__ volatile int g_bar_gen;

// bf16 split operands
__device__ __nv_bfloat16 g_ebh[(size_t)VOC * HID];
__device__ __nv_bfloat16 g_ebl[(size_t)VOC * HID];
__device__ __nv_bfloat16 g_wh [(size_t)GATES * HID];
__device__ __nv_bfloat16 g_wl [(size_t)GATES * HID];
__device__ __nv_bfloat16 g_rwh[(size_t)GATES * HID];   // w_hh hi
__device__ __nv_bfloat16 g_rwl[(size_t)GATES * HID];   // w_hh lo
__device__ __nv_bfloat16 g_xh [(size_t)MM * HID];
__device__ __nv_bfloat16 g_xl [(size_t)MM * HID];
__device__ __nv_bfloat16 g_hh2[(size_t)MM * HID];      // h_all hi (decoder A)
__device__ __nv_bfloat16 g_hl2[(size_t)MM * HID];      // h_all lo

// ---------------- helpers ----------------
__device__ __forceinline__ void cpasync16(uint32_t dst, const void* src) {
    asm volatile("cp.async.cg.shared.global [%0], [%1], 16;\n" :: "r"(dst), "l"(src));
}
#define CP_COMMIT() asm volatile("cp.async.commit_group;\n")

__device__ __forceinline__ float fexp(float x) {
    float y = fmaxf(x * 1.4426950408889634f, -120.f);
    float n = rintf(y);
    float f = y - n;
    float p = 0.0013333558f;
    p = fmaf(p, f, 0.0096181291f);
    p = fmaf(p, f, 0.0555041087f);
    p = fmaf(p, f, 0.2402265069f);
    p = fmaf(p, f, 0.6931471806f);
    p = fmaf(p, f, 1.0f);
    return p * __int_as_float(((int)n + 127) << 23);
}

__device__ __forceinline__ void mma16816(float* d, const uint32_t* a, const uint32_t* b) {
    asm volatile(
        "mma.sync.aligned.m16n8k16.row.col.f32.bf16.bf16.f32 "
        "{%0,%1,%2,%3}, {%4,%5,%6,%7}, {%8,%9}, {%0,%1,%2,%3};"
        : "+f"(d[0]), "+f"(d[1]), "+f"(d[2]), "+f"(d[3])
        : "r"(a[0]), "r"(a[1]), "r"(a[2]), "r"(a[3]), "r"(b[0]), "r"(b[1]));
}

__device__ __forceinline__ uint32_t pkbf(float a, float b) {
    return ((uint32_t)__bfloat16_as_ushort(__float2bfloat16(b)) << 16)
         | __bfloat16_as_ushort(__float2bfloat16(a));
}
// split 8 floats -> 8 bf16 hi + 8 bf16 lo (as uint4 each)
__device__ __forceinline__ void split8(float4 a, float4 b, uint4& ph, uint4& pl) {
    float h0 = __bfloat162float(__float2bfloat16(a.x));
    float h1 = __bfloat162float(__float2bfloat16(a.y));
    float h2 = __bfloat162float(__float2bfloat16(a.z));
    float h3 = __bfloat162float(__float2bfloat16(a.w));
    float h4 = __bfloat162float(__float2bfloat16(b.x));
    float h5 = __bfloat162float(__float2bfloat16(b.y));
    float h6 = __bfloat162float(__float2bfloat16(b.z));
    float h7 = __bfloat162float(__float2bfloat16(b.w));
    ph.x = pkbf(a.x, a.y); ph.y = pkbf(a.z, a.w);
    ph.z = pkbf(b.x, b.y); ph.w = pkbf(b.z, b.w);
    pl.x = pkbf(a.x - h0, a.y - h1); pl.y = pkbf(a.z - h2, a.w - h3);
    pl.z = pkbf(b.x - h4, b.y - h5); pl.w = pkbf(b.z - h6, b.w - h7);
}

// ---------------- small kernels ----------------
__global__ void zero_state_kernel() {
    int i = blockIdx.x * blockDim.x + threadIdx.x;
    if (i < BB * HID) { g_hbuf[0][i] = 0.f; g_c[i] = 0.f; }
    if (i < 128 * 32) g_bar_flags[i] = 0;
    if (i == 0) g_bar_gen = 0;
}

// gather + split fused: xh/xl[(t*8+b)] = split(emb_W[x[b][t]])
__global__ void gather_kernel(const int* __restrict__ x, const float* __restrict__ embW,
                              __nv_bfloat16* __restrict__ xh, __nv_bfloat16* __restrict__ xl) {
    int m = blockIdx.x;                     // m = t*8+b
    int t = m >> 3, b = m & 7;
    int tok = x[b * TT + t];
    const float4* src = (const float4*)(embW + (size_t)tok * HID);
    int i = threadIdx.x;                    // 0..127, 8 floats each
    float4 a = src[2 * i], c = src[2 * i + 1];
    uint4 ph, pl;
    split8(a, c, ph, pl);
    ((uint4*)(xh + (size_t)m * HID))[i] = ph;
    ((uint4*)(xl + (size_t)m * HID))[i] = pl;
}

// vectorized split: n8 = n/8 octets
__global__ void split_kernel(const float* __restrict__ s, __nv_bfloat16* __restrict__ h,
                             __nv_bfloat16* __restrict__ l, long n8) {
    long i = blockIdx.x * (long)blockDim.x + threadIdx.x;
    long st = (long)gridDim.x * blockDim.x;
    const float4* s4 = (const float4*)s;
    for (; i < n8; i += st) {
        float4 a = s4[2 * i], b = s4[2 * i + 1];
        uint4 ph, pl;
        split8(a, b, ph, pl);
        ((uint4*)h)[i] = ph;
        ((uint4*)l)[i] = pl;
    }
}

// ---------------- mma.sync split-bf16 NT GEMM (unchanged, passing) ----------------
#define BKP 40
#define BUF_B (128 * BKP * 2)
#define STAGE_B (4 * BUF_B)
#define MMSMEM (2 * STAGE_B)

__device__ __forceinline__ void stage_chunk_mma(
    char* smem, int stage, int tid, int kc,
    const __nv_bfloat16* Ah, const __nv_bfloat16* Al,
    const __nv_bfloat16* Bh, const __nv_bfloat16* Bl,
    int m0, int n0, int Nrows, int K)
{
    uint32_t sb = (uint32_t)__cvta_generic_to_shared(smem) + (uint32_t)stage * STAGE_B;
    #pragma unroll
    for (int i = 0; i < 8; i++) {
        int u = tid + 256 * i;
        int buf = u >> 9;
        int o = u & 511;
        int row = o >> 2;
        int col = (o & 3) * 8;
        const __nv_bfloat16* src;
        if (buf < 2) {
            src = ((buf == 0) ? Ah : Al) + (size_t)(m0 + row) * K + kc + col;
        } else {
            int n = n0 + row; if (n >= Nrows) n = Nrows - 1;
            src = ((buf == 2) ? Bh : Bl) + (size_t)n * K + kc + col;
        }
        cpasync16(sb + (uint32_t)(buf * BUF_B + (row * BKP + col) * 2), src);
    }
}

__global__ void __launch_bounds__(256)
mm_bf16_kernel(const __nv_bfloat16* __restrict__ Ah, const __nv_bfloat16* __restrict__ Al,
               const __nv_bfloat16* __restrict__ Bh, const __nv_bfloat16* __restrict__ Bl,
               const float* __restrict__ bias1, const float* __restrict__ bias2,
               float* __restrict__ C, int Nrows, int ldc, int K)
{
    extern __shared__ char smem[];
    int tid = threadIdx.x;
    int wid = tid >> 5, lane = tid & 31;
    int m0 = blockIdx.x * 128;
    int n0 = blockIdx.y * 128;
    int m0w = (wid >> 2) * 64;
    int n0w = (wid & 3) * 32;
    const int NC = K / 32;

    float acc[4][4][4];
    #pragma unroll
    for (int mf = 0; mf < 4; mf++)
        #pragma unroll
        for (int nf = 0; nf < 4; nf++)
            #pragma unroll
            for (int e = 0; e < 4; e++) acc[mf][nf][e] = 0.f;

    stage_chunk_mma(smem, 0, tid, 0, Ah, Al, Bh, Bl, m0, n0, Nrows, K);
    CP_COMMIT();
    stage_chunk_mma(smem, 1, tid, 32, Ah, Al, Bh, Bl, m0, n0, Nrows, K);
    CP_COMMIT();

    int ar = lane >> 2;
    int ac = (lane & 3) * 2;

    for (int c = 0; c < NC; c++) {
        if (c < NC - 1) asm volatile("cp.async.wait_group 1;" ::: "memory");
        else            asm volatile("cp.async.wait_group 0;" ::: "memory");
        __syncthreads();

        const __nv_bfloat16* st = (const __nv_bfloat16*)(smem + (c & 1) * STAGE_B);
        const __nv_bfloat16* pAh = st;
        const __nv_bfloat16* pAl = st + 128 * BKP;
        const __nv_bfloat16* pBh = st + 2 * 128 * BKP;
        const __nv_bfloat16* pBl = st + 3 * 128 * BKP;

        #pragma unroll
        for (int ks = 0; ks < 32; ks += 16) {
            uint32_t fAh[4][4], fAl[4][4], fBh[4][2], fBl[4][2];
            #pragma unroll
            for (int mf = 0; mf < 4; mf++) {
                int r = m0w + mf * 16 + ar;
                int cc = ks + ac;
                fAh[mf][0] = *(const uint32_t*)(pAh + r * BKP + cc);
                fAh[mf][1] = *(const uint32_t*)(pAh + (r + 8) * BKP + cc);
                fAh[mf][2] = *(const uint32_t*)(pAh + r * BKP + cc + 8);
                fAh[mf][3] = *(const uint32_t*)(pAh + (r + 8) * BKP + cc + 8);
                fAl[mf][0] = *(const uint32_t*)(pAl + r * BKP + cc);
                fAl[mf][1] = *(const uint32_t*)(pAl + (r + 8) * BKP + cc);
                fAl[mf][2] = *(const uint32_t*)(pAl + r * BKP + cc + 8);
                fAl[mf][3] = *(const uint32_t*)(pAl + (r + 8) * BKP + cc + 8);
            }
            #pragma unroll
            for (int nf = 0; nf < 4; nf++) {
                int n = n0w + nf * 8 + ar;
                int kk = ks + ac;
                fBh[nf][0] = *(const uint32_t*)(pBh + n * BKP + kk);
                fBh[nf][1] = *(const uint32_t*)(pBh + n * BKP + kk + 8);
                fBl[nf][0] = *(const uint32_t*)(pBl + n * BKP + kk);
                fBl[nf][1] = *(const uint32_t*)(pBl + n * BKP + kk + 8);
            }
            #pragma unroll
            for (int mf = 0; mf < 4; mf++)
                #pragma unroll
                for (int nf = 0; nf < 4; nf++) {
                    mma16816(acc[mf][nf], fAh[mf], fBh[nf]);
                    mma16816(acc[mf][nf], fAh[mf], fBl[nf]);
                    mma16816(acc[mf][nf], fAl[mf], fBh[nf]);
                }
        }
        __syncthreads();
        if (c + 2 < NC) {
            stage_chunk_mma(smem, c & 1, tid, (c + 2) * 32, Ah, Al, Bh, Bl, m0, n0, Nrows, K);
            CP_COMMIT();
        }
    }

    // epilogue: scalar stores (ldc may be odd)
    #pragma unroll
    for (int mf = 0; mf < 4; mf++) {
        int row0 = m0 + m0w + mf * 16 + ar;
        float* r0p = C + (size_t)row0 * ldc;
        float* r1p = C + (size_t)(row0 + 8) * ldc;
        #pragma unroll
        for (int nf = 0; nf < 4; nf++) {
            int col = n0 + n0w + nf * 8 + ac;
            #pragma unroll
            for (int e = 0; e < 2; e++) {
                int cc = col + e;
                if (cc < Nrows) {
                    float bv = 0.f;
                    if (bias1) bv += bias1[cc];
                    if (bias2) bv += bias2[cc];
                    r0p[cc] = acc[mf][nf][e] + bv;
                    r1p[cc] = acc[mf][nf][2 + e] + bv;
                }
            }
        }
    }
}

// ---------------- persistent LSTM, flag-array grid barrier ----------------
#define WPAD 1032
#define LP_SWH 0
#define LP_SWL 66048
#define LP_SHH 132096
#define LP_SHL 148608
#define LP_RED 165120
#define LP_GATES 173312
#define LP_SMEM 174336

__global__ void __launch_bounds__(256)
lstm_persistent_kernel(const __nv_bfloat16* __restrict__ rwh,
                       const __nv_bfloat16* __restrict__ rwl)
{
    extern __shared__ char smraw[];
    __nv_bfloat16* swh = (__nv_bfloat16*)(smraw + LP_SWH);
    __nv_bfloat16* swl = (__nv_bfloat16*)(smraw + LP_SWL);
    __nv_bfloat16* shh = (__nv_bfloat16*)(smraw + LP_SHH);
    __nv_bfloat16* shl = (__nv_bfloat16*)(smraw + LP_SHL);
    float* red      = (float*)(smraw + LP_RED);
    float* sm_gates = (float*)(smraw + LP_GATES);

    int tid = threadIdx.x;
    int jb = blockIdx.x * 8;

    // one-time weight staging (hi+lo)
    {
        uint32_t sb = (uint32_t)__cvta_generic_to_shared(smraw);
        #pragma unroll
        for (int i = 0; i < 32; i++) {
            int u = tid + 256 * i;
            int buf = u >> 12;
            int o = u & 4095;
            int row = o >> 7;
            int ch = o & 127;
            int g = row >> 3, jl = row & 7;
            const __nv_bfloat16* src = (buf ? rwl : rwh)
                + (size_t)(g * HID + jb + jl) * HID + ch * 8;
            cpasync16(sb + (uint32_t)(buf * LP_SWL + row * (WPAD * 2) + ch * 16), src);
        }
        CP_COMMIT();
        asm volatile("cp.async.wait_group 0;\n" ::: "memory");
        __syncthreads();
    }

    int wid = tid >> 5, lane = tid & 31;
    int ar = lane >> 2;
    int ac = (lane & 3) * 2;
    int ejl = tid >> 3, eb = tid & 7;
    float c_reg = 0.f;

    for (int t = 0; t < TT; t++) {
        const float* hprev = g_hbuf[t & 1];
        float* hnext = g_hbuf[(t + 1) & 1];

        // stage h: fp32 -> bf16 hi/lo smem
        {
            const float4* hp4 = (const float4*)hprev;
            #pragma unroll
            for (int i = 0; i < 8; i++) {
                int f4 = tid + 256 * i;
                float4 v = __ldcg(hp4 + f4);
                int batch = f4 >> 8;
                int k = (f4 & 255) * 4;
                int off = batch * WPAD + k;
                uint4 dummy;
                float h0 = __bfloat162float(__float2bfloat16(v.x));
                float h1 = __bfloat162float(__float2bfloat16(v.y));
                float h2 = __bfloat162float(__float2bfloat16(v.z));
                float h3 = __bfloat162float(__float2bfloat16(v.w));
                uint2 ph, pl;
                ph.x = pkbf(v.x, v.y);
                ph.y = pkbf(v.z, v.w);
                pl.x = pkbf(v.x - h0, v.y - h1);
                pl.y = pkbf(v.z - h2, v.w - h3);
                (void)dummy;
                *(uint2*)(shh + off) = ph;
                *(uint2*)(shl + off) = pl;
            }
        }
        __syncthreads();

        // recurrent GEMM: warp wid handles k in [wid*128, wid*128+128)
        float acc[2][4];
        #pragma unroll
        for (int mt = 0; mt < 2; mt++)
            #pragma unroll
            for (int e = 0; e < 4; e++) acc[mt][e] = 0.f;

        #pragma unroll
        for (int ks8 = 0; ks8 < 8; ks8++) {
            int kk = wid * 128 + ks8 * 16;
            uint32_t bh[2], bl[2];
            bh[0] = *(const uint32_t*)(shh + ar * WPAD + kk + ac);
            bh[1] = *(const uint32_t*)(shh + ar * WPAD + kk + ac + 8);
            bl[0] = *(const uint32_t*)(shl + ar * WPAD + kk + ac);
            bl[1] = *(const uint32_t*)(shl + ar * WPAD + kk + ac + 8);
            #pragma unroll
            for (int mt = 0; mt < 2; mt++) {
                int r = mt * 16 + ar;
                uint32_t ah[4], al[4];
                ah[0] = *(const uint32_t*)(swh + r * WPAD + kk + ac);
                ah[1] = *(const uint32_t*)(swh + (r + 8) * WPAD + kk + ac);
                ah[2] = *(const uint32_t*)(swh + r * WPAD + kk + ac + 8);
                ah[3] = *(const uint32_t*)(swh + (r + 8) * WPAD + kk + ac + 8);
                al[0] = *(const uint32_t*)(swl + r * WPAD + kk + ac);
                al[1] = *(const uint32_t*)(swl + (r + 8) * WPAD + kk + ac);
                al[2] = *(const uint32_t*)(swl + r * WPAD + kk + ac + 8);
                al[3] = *(const uint32_t*)(swl + (r + 8) * WPAD + kk + ac + 8);
                mma16816(acc[mt], ah, bh);
                mma16816(acc[mt], ah, bl);
                mma16816(acc[mt], al, bh);
            }
        }

        // cross-warp k-reduce
        #pragma unroll
        for (int mt = 0; mt < 2; mt++)
            #pragma unroll
            for (int e = 0; e < 4; e++) {
                int row = mt * 16 + ar + ((e & 2) ? 8 : 0);
                int b = ac + (e & 1);
                red[row * 64 + b * 8 + wid] = acc[mt][e];
            }
        __syncthreads();

        {
            float4 p0 = *(float4*)(red + tid * 8);
            float4 p1 = *(float4*)(red + tid * 8 + 4);
            int row = tid >> 3, b = tid & 7;
            int g = row >> 3, jl = row & 7;
            sm_gates[tid] = ((p0.x + p0.y) + (p0.z + p0.w))
                          + ((p1.x + p1.y) + (p1.z + p1.w))
                          + g_xproj[((size_t)t * BB + b) * GATES + g * HID + jb + jl];
        }
        __syncthreads();

        if (tid < 64) {
            int j = jb + ejl;
            float gi = sm_gates[(0 * 8 + ejl) * 8 + eb];
            float gf = sm_gates[(1 * 8 + ejl) * 8 + eb];
            float gg = sm_gates[(2 * 8 + ejl) * 8 + eb];
            float go = sm_gates[(3 * 8 + ejl) * 8 + eb];
            gi = 1.f / (1.f + expf(-gi));
            gf = 1.f / (1.f + expf(-gf));
            gg = tanhf(gg);
            go = 1.f / (1.f + expf(-go));
            c_reg = gf * c_reg + gi * gg;
            float h = go * tanhf(c_reg);
            hnext[eb * HID + j] = h;
            // fused decoder-operand split (replaces g_hall + split pass)
            size_t di = ((size_t)eb * TT + t) * HID + j;
            float hh = __bfloat162float(__float2bfloat16(h));
            g_hh2[di] = __float2bfloat16(h);
            g_hl2[di] = __float2bfloat16(h - hh);
            if (t == TT - 1) g_c[eb * HID + j] = c_reg;
        }

        // ---- flag-array grid barrier ----
        __syncthreads();
        __threadfence();
        if (tid == 0)
            *(volatile int*)&g_bar_flags[blockIdx.x * 32] = t + 1;
        if (blockIdx.x == 0) {
            if (wid == 0) {
                int idx = lane * 4;
                for (;;) {
                    int ok = 1;
                    #pragma unroll
                    for (int q = 0; q < 4; q++)
                        ok &= (*(volatile int*)&g_bar_flags[(idx + q) * 32] >= t + 1);
                    if (__all_sync(0xffffffffu, ok)) break;
                }
                __threadfence();
                if (lane == 0) g_bar_gen = t + 1;
            }
        } else {
            if (tid == 0) {
                while (g_bar_gen < t + 1) { }
            }
        }
        __syncthreads();
    }
}

// ---------------- log-softmax ----------------
__global__ void __launch_bounds__(256)
row_lse_kernel(const float* __restrict__ logits)
{
    int row = blockIdx.x;
    const float* p = logits + (size_t)row * VOC;
    float m = -1e30f, s = 0.f;
    for (int i = threadIdx.x; i < VOC; i += 256) {
        float v = p[i];
        if (v > m) { s = s * fexp(m - v) + 1.f; m = v; }
        else       { s += fexp(v - m); }
    }
    __shared__ float sm[256], ss[256];
    sm[threadIdx.x] = m; ss[threadIdx.x] = s;
    __syncthreads();
    for (int off = 128; off; off >>= 1) {
        if (threadIdx.x < off) {
            float m1 = sm[threadIdx.x], s1 = ss[threadIdx.x];
            float m2 = sm[threadIdx.x + off], s2 = ss[threadIdx.x + off];
            float mm = fmaxf(m1, m2);
            sm[threadIdx.x] = mm;
            ss[threadIdx.x] = s1 * fexp(m1 - mm) + s2 * fexp(m2 - mm);
        }
        __syncthreads();
    }
    if (threadIdx.x == 0) g_lse[row] = sm[0] + logf(ss[0]);
}

__global__ void __launch_bounds__(256)
sub_lse_kernel(float* __restrict__ out)
{
    int row = blockIdx.x;
    float l = g_lse[row];
    float* p = out + (size_t)row * VOC;
    for (int i = threadIdx.x; i < VOC; i += 256) p[i] -= l;
}

__global__ void write_hidden_kernel(float* __restrict__ out)
{
    int i = blockIdx.x * blockDim.x + threadIdx.x;
    size_t base = (size_t)MM * VOC;
    if (i < BB * HID)               out[base + i] = g_hbuf[0][i];
    else if (i < 2 * BB * HID)      out[base + i] = g_c[i - BB * HID];
}

// ---------------- launcher ----------------
extern "C" void kernel_launch(void* const* d_in, const int* in_sizes, int n_in,
                              void* d_out, int out_size)
{
    const int*   x     = (const int*)  d_in[0];
    const float* emb_W = (const float*)d_in[1];
    const float* w_ih  = (const float*)d_in[2];
    const float* w_hh  = (const float*)d_in[3];
    const float* b_ih  = (const float*)d_in[4];
    const float* b_hh  = (const float*)d_in[5];
    const float* dec_b = (const float*)d_in[6];
    float* out = (float*)d_out;

    float* xproj_p; cudaGetSymbolAddress((void**)&xproj_p, g_xproj);
    __nv_bfloat16 *ebh, *ebl, *wh, *wl, *rwh, *rwl, *xh, *xl, *hh2, *hl2;
    cudaGetSymbolAddress((void**)&ebh, g_ebh);
    cudaGetSymbolAddress((void**)&ebl, g_ebl);
    cudaGetSymbolAddress((void**)&wh,  g_wh);
    cudaGetSymbolAddress((void**)&wl,  g_wl);
    cudaGetSymbolAddress((void**)&rwh, g_rwh);
    cudaGetSymbolAddress((void**)&rwl, g_rwl);
    cudaGetSymbolAddress((void**)&xh,  g_xh);
    cudaGetSymbolAddress((void**)&xl,  g_xl);
    cudaGetSymbolAddress((void**)&hh2, g_hh2);
    cudaGetSymbolAddress((void**)&hl2, g_hl2);

    cudaFuncSetAttribute(lstm_persistent_kernel,
                         cudaFuncAttributeMaxDynamicSharedMemorySize, LP_SMEM);
    cudaFuncSetAttribute(mm_bf16_kernel,
                         cudaFuncAttributeMaxDynamicSharedMemorySize, MMSMEM);

    zero_state_kernel<<<(BB * HID + 255) / 256, 256>>>();

    // gather + split fused (xh/xl directly from embedding rows)
    gather_kernel<<<MM, 128>>>(x, emb_W, xh, xl);

    // vectorized splits
    split_kernel<<<4096, 256>>>(emb_W, ebh, ebl, (long)VOC * HID / 8);
    split_kernel<<<512,  256>>>(w_ih,  wh,  wl,  (long)GATES * HID / 8);
    split_kernel<<<512,  256>>>(w_hh,  rwh, rwl, (long)GATES * HID / 8);

    // x_proj = emb @ w_ih^T + (b_ih + b_hh)
    {
        dim3 grid(MM / 128, GATES / 128);
        mm_bf16_kernel<<<grid, 256, MMSMEM>>>(xh, xl, wh, wl, b_ih, b_hh,
                                              xproj_p, GATES, GATES, HID);
    }

    // all 256 LSTM steps (persistent; epilogue emits decoder operands)
    lstm_persistent_kernel<<<HID / 8, 256, LP_SMEM>>>(rwh, rwl);

    // decoder: logits = h_all @ emb_W^T + dec_b
    {
        dim3 grid(MM / 128, (VOC + 127) / 128);
        mm_bf16_kernel<<<grid, 256, MMSMEM>>>(hh2, hl2, ebh, ebl, dec_b,
                                              (const float*)0, out, VOC, VOC, HID);
    }

    row_lse_kernel<<<MM, 256>>>(out);
    sub_lse_kernel<<<MM, 256>>>(out);

    if (out_size >= MM * VOC + 2 * BB * HID)
        write_hidden_kernel<<<(2 * BB * HID + 255) / 256, 256>>>(out);
}

// round 11
// speedup vs baseline: 1.1266x; 1.1078x over previous
#include <cuda_runtime.h>
#include <cuda_bf16.h>
#include <math.h>
#include <stdint.h>

#define HID   1024
#define GATES 4096
#define BB    8
#define TT    256
#define MM    2048
#define VOC   50257
#define NPART ((VOC + 127) / 128)      // 393 decoder column tiles

typedef unsigned long long u64;

// ---------------- scratch ----------------
__device__ float g_xproj[(size_t)GATES * MM];       // TRANSPOSED: [gate][m]
__device__ float g_hbuf[2][BB * HID];
__device__ float g_c[BB * HID];
__device__ float g_lse[MM];
__device__ float2 g_lsepart[(size_t)MM * NPART];
__device__ int   g_bar_flags[128 * 32];             // one flag per CTA, 128B apart

// bf16 split operands
__device__ __nv_bfloat16 g_ebh[(size_t)VOC * HID];
__device__ __nv_bfloat16 g_ebl[(size_t)VOC * HID];
__device__ __nv_bfloat16 g_wh [(size_t)GATES * HID];
__device__ __nv_bfloat16 g_wl [(size_t)GATES * HID];
__device__ __nv_bfloat16 g_rwh[(size_t)GATES * HID];
__device__ __nv_bfloat16 g_rwl[(size_t)GATES * HID];
__device__ __nv_bfloat16 g_xh [(size_t)MM * HID];
__device__ __nv_bfloat16 g_xl [(size_t)MM * HID];
__device__ __nv_bfloat16 g_hh2[(size_t)MM * HID];
__device__ __nv_bfloat16 g_hl2[(size_t)MM * HID];

// ---------------- helpers ----------------
__device__ __forceinline__ void cpasync16(uint32_t dst, const void* src) {
    asm volatile("cp.async.cg.shared.global [%0], [%1], 16;\n" :: "r"(dst), "l"(src));
}
#define CP_COMMIT() asm volatile("cp.async.commit_group;\n")

__device__ __forceinline__ float fexp(float x) {
    float y = fmaxf(x * 1.4426950408889634f, -120.f);
    float n = rintf(y);
    float f = y - n;
    float p = 0.0013333558f;
    p = fmaf(p, f, 0.0096181291f);
    p = fmaf(p, f, 0.0555041087f);
    p = fmaf(p, f, 0.2402265069f);
    p = fmaf(p, f, 0.6931471806f);
    p = fmaf(p, f, 1.0f);
    return p * __int_as_float(((int)n + 127) << 23);
}

__device__ __forceinline__ void mma16816(float* d, const uint32_t* a, const uint32_t* b) {
    asm volatile(
        "mma.sync.aligned.m16n8k16.row.col.f32.bf16.bf16.f32 "
        "{%0,%1,%2,%3}, {%4,%5,%6,%7}, {%8,%9}, {%0,%1,%2,%3};"
        : "+f"(d[0]), "+f"(d[1]), "+f"(d[2]), "+f"(d[3])
        : "r"(a[0]), "r"(a[1]), "r"(a[2]), "r"(a[3]), "r"(b[0]), "r"(b[1]));
}

__device__ __forceinline__ uint32_t pkbf(float a, float b) {
    return ((uint32_t)__bfloat16_as_ushort(__float2bfloat16(b)) << 16)
         | __bfloat16_as_ushort(__float2bfloat16(a));
}
__device__ __forceinline__ void split8(float4 a, float4 b, uint4& ph, uint4& pl) {
    float h0 = __bfloat162float(__float2bfloat16(a.x));
    float h1 = __bfloat162float(__float2bfloat16(a.y));
    float h2 = __bfloat162float(__float2bfloat16(a.z));
    float h3 = __bfloat162float(__float2bfloat16(a.w));
    float h4 = __bfloat162float(__float2bfloat16(b.x));
    float h5 = __bfloat162float(__float2bfloat16(b.y));
    float h6 = __bfloat162float(__float2bfloat16(b.z));
    float h7 = __bfloat162float(__float2bfloat16(b.w));
    ph.x = pkbf(a.x, a.y); ph.y = pkbf(a.z, a.w);
    ph.z = pkbf(b.x, b.y); ph.w = pkbf(b.z, b.w);
    pl.x = pkbf(a.x - h0, a.y - h1); pl.y = pkbf(a.z - h2, a.w - h3);
    pl.z = pkbf(b.x - h4, b.y - h5); pl.w = pkbf(b.z - h6, b.w - h7);
}

// ---------------- small kernels ----------------
__global__ void zero_state_kernel() {
    int i = blockIdx.x * blockDim.x + threadIdx.x;
    if (i < BB * HID) { g_hbuf[0][i] = 0.f; g_c[i] = 0.f; }
    if (i < 128 * 32) g_bar_flags[i] = 0;
}

__global__ void gather_kernel(const int* __restrict__ x, const float* __restrict__ embW,
                              __nv_bfloat16* __restrict__ xh, __nv_bfloat16* __restrict__ xl) {
    int m = blockIdx.x;
    int t = m >> 3, b = m & 7;
    int tok = x[b * TT + t];
    const float4* src = (const float4*)(embW + (size_t)tok * HID);
    int i = threadIdx.x;
    float4 a = src[2 * i], c = src[2 * i + 1];
    uint4 ph, pl;
    split8(a, c, ph, pl);
    ((uint4*)(xh + (size_t)m * HID))[i] = ph;
    ((uint4*)(xl + (size_t)m * HID))[i] = pl;
}

__global__ void split_kernel(const float* __restrict__ s, __nv_bfloat16* __restrict__ h,
                             __nv_bfloat16* __restrict__ l, long n8) {
    long i = blockIdx.x * (long)blockDim.x + threadIdx.x;
    long st = (long)gridDim.x * blockDim.x;
    const float4* s4 = (const float4*)s;
    for (; i < n8; i += st) {
        float4 a = s4[2 * i], b = s4[2 * i + 1];
        uint4 ph, pl;
        split8(a, b, ph, pl);
        ((uint4*)h)[i] = ph;
        ((uint4*)l)[i] = pl;
    }
}

// ---------------- mma.sync split-bf16 NT GEMM ----------------
// Optional fused log-sum-exp partials per 128-row x 128-col tile (lse_part != null).
#define BKP 40
#define BUF_B (128 * BKP * 2)
#define STAGE_B (4 * BUF_B)
#define MMSMEM (2 * STAGE_B)

__device__ __forceinline__ void stage_chunk_mma(
    char* smem, int stage, int tid, int kc,
    const __nv_bfloat16* Ah, const __nv_bfloat16* Al,
    const __nv_bfloat16* Bh, const __nv_bfloat16* Bl,
    int m0, int n0, int Nrows, int K)
{
    uint32_t sb = (uint32_t)__cvta_generic_to_shared(smem) + (uint32_t)stage * STAGE_B;
    #pragma unroll
    for (int i = 0; i < 8; i++) {
        int u = tid + 256 * i;
        int buf = u >> 9;
        int o = u & 511;
        int row = o >> 2;
        int col = (o & 3) * 8;
        const __nv_bfloat16* src;
        if (buf < 2) {
            src = ((buf == 0) ? Ah : Al) + (size_t)(m0 + row) * K + kc + col;
        } else {
            int n = n0 + row; if (n >= Nrows) n = Nrows - 1;
            src = ((buf == 2) ? Bh : Bl) + (size_t)n * K + kc + col;
        }
        cpasync16(sb + (uint32_t)(buf * BUF_B + (row * BKP + col) * 2), src);
    }
}

__global__ void __launch_bounds__(256)
mm_bf16_kernel(const __nv_bfloat16* __restrict__ Ah, const __nv_bfloat16* __restrict__ Al,
               const __nv_bfloat16* __restrict__ Bh, const __nv_bfloat16* __restrict__ Bl,
               const float* __restrict__ bias1, const float* __restrict__ bias2,
               float* __restrict__ C, int Nrows, int ldc, int K,
               float2* __restrict__ lse_part)
{
    extern __shared__ char smem[];
    int tid = threadIdx.x;
    int wid = tid >> 5, lane = tid & 31;
    int m0 = blockIdx.x * 128;
    int n0 = blockIdx.y * 128;
    int m0w = (wid >> 2) * 64;
    int n0w = (wid & 3) * 32;
    const int NC = K / 32;

    float acc[4][4][4];
    #pragma unroll
    for (int mf = 0; mf < 4; mf++)
        #pragma unroll
        for (int nf = 0; nf < 4; nf++)
            #pragma unroll
            for (int e = 0; e < 4; e++) acc[mf][nf][e] = 0.f;

    stage_chunk_mma(smem, 0, tid, 0, Ah, Al, Bh, Bl, m0, n0, Nrows, K);
    CP_COMMIT();
    stage_chunk_mma(smem, 1, tid, 32, Ah, Al, Bh, Bl, m0, n0, Nrows, K);
    CP_COMMIT();

    int ar = lane >> 2;
    int ac = (lane & 3) * 2;

    for (int c = 0; c < NC; c++) {
        if (c < NC - 1) asm volatile("cp.async.wait_group 1;" ::: "memory");
        else            asm volatile("cp.async.wait_group 0;" ::: "memory");
        __syncthreads();

        const __nv_bfloat16* st = (const __nv_bfloat16*)(smem + (c & 1) * STAGE_B);
        const __nv_bfloat16* pAh = st;
        const __nv_bfloat16* pAl = st + 128 * BKP;
        const __nv_bfloat16* pBh = st + 2 * 128 * BKP;
        const __nv_bfloat16* pBl = st + 3 * 128 * BKP;

        #pragma unroll
        for (int ks = 0; ks < 32; ks += 16) {
            uint32_t fAh[4][4], fAl[4][4], fBh[4][2], fBl[4][2];
            #pragma unroll
            for (int mf = 0; mf < 4; mf++) {
                int r = m0w + mf * 16 + ar;
                int cc = ks + ac;
                fAh[mf][0] = *(const uint32_t*)(pAh + r * BKP + cc);
                fAh[mf][1] = *(const uint32_t*)(pAh + (r + 8) * BKP + cc);
                fAh[mf][2] = *(const uint32_t*)(pAh + r * BKP + cc + 8);
                fAh[mf][3] = *(const uint32_t*)(pAh + (r + 8) * BKP + cc + 8);
                fAl[mf][0] = *(const uint32_t*)(pAl + r * BKP + cc);
                fAl[mf][1] = *(const uint32_t*)(pAl + (r + 8) * BKP + cc);
                fAl[mf][2] = *(const uint32_t*)(pAl + r * BKP + cc + 8);
                fAl[mf][3] = *(const uint32_t*)(pAl + (r + 8) * BKP + cc + 8);
            }
            #pragma unroll
            for (int nf = 0; nf < 4; nf++) {
                int n = n0w + nf * 8 + ar;
                int kk = ks + ac;
                fBh[nf][0] = *(const uint32_t*)(pBh + n * BKP + kk);
                fBh[nf][1] = *(const uint32_t*)(pBh + n * BKP + kk + 8);
                fBl[nf][0] = *(const uint32_t*)(pBl + n * BKP + kk);
                fBl[nf][1] = *(const uint32_t*)(pBl + n * BKP + kk + 8);
            }
            #pragma unroll
            for (int mf = 0; mf < 4; mf++)
                #pragma unroll
                for (int nf = 0; nf < 4; nf++) {
                    mma16816(acc[mf][nf], fAh[mf], fBh[nf]);
                    mma16816(acc[mf][nf], fAh[mf], fBl[nf]);
                    mma16816(acc[mf][nf], fAl[mf], fBh[nf]);
                }
        }
        __syncthreads();
        if (c + 2 < NC) {
            stage_chunk_mma(smem, c & 1, tid, (c + 2) * 32, Ah, Al, Bh, Bl, m0, n0, Nrows, K);
            CP_COMMIT();
        }
    }

    // epilogue: scalar stores + optional online (max, sumexp) per row
    float rmax[4][2], rsum[4][2];
    #pragma unroll
    for (int mf = 0; mf < 4; mf++) { rmax[mf][0] = rmax[mf][1] = -1e30f; rsum[mf][0] = rsum[mf][1] = 0.f; }

    #pragma unroll
    for (int mf = 0; mf < 4; mf++) {
        int row0 = m0 + m0w + mf * 16 + ar;
        float* r0p = C + (size_t)row0 * ldc;
        float* r1p = C + (size_t)(row0 + 8) * ldc;
        #pragma unroll
        for (int nf = 0; nf < 4; nf++) {
            int col = n0 + n0w + nf * 8 + ac;
            #pragma unroll
            for (int e = 0; e < 2; e++) {
                int cc = col + e;
                if (cc < Nrows) {
                    float bv = 0.f;
                    if (bias1) bv += bias1[cc];
                    if (bias2) bv += bias2[cc];
                    float v0 = acc[mf][nf][e] + bv;
                    float v1 = acc[mf][nf][2 + e] + bv;
                    r0p[cc] = v0;
                    r1p[cc] = v1;
                    if (lse_part) {
                        if (v0 > rmax[mf][0]) { rsum[mf][0] = rsum[mf][0] * fexp(rmax[mf][0] - v0) + 1.f; rmax[mf][0] = v0; }
                        else                  { rsum[mf][0] += fexp(v0 - rmax[mf][0]); }
                        if (v1 > rmax[mf][1]) { rsum[mf][1] = rsum[mf][1] * fexp(rmax[mf][1] - v1) + 1.f; rmax[mf][1] = v1; }
                        else                  { rsum[mf][1] += fexp(v1 - rmax[mf][1]); }
                    }
                }
            }
        }
    }

    if (lse_part) {
        // quad reduce: lanes ar*4..ar*4+3 share rows
        #pragma unroll
        for (int mf = 0; mf < 4; mf++)
            #pragma unroll
            for (int h = 0; h < 2; h++) {
                float m = rmax[mf][h], s = rsum[mf][h];
                #pragma unroll
                for (int off = 1; off <= 2; off <<= 1) {
                    float m2 = __shfl_xor_sync(0xffffffffu, m, off);
                    float s2 = __shfl_xor_sync(0xffffffffu, s, off);
                    float mm = fmaxf(m, m2);
                    s = s * fexp(m - mm) + s2 * fexp(m2 - mm);
                    m = mm;
                }
                rmax[mf][h] = m; rsum[mf][h] = s;
            }
        __syncthreads();                       // smem now reusable
        float2* sp = (float2*)smem;            // [128 rows][4 warps]
        if ((lane & 3) == 0) {
            #pragma unroll
            for (int mf = 0; mf < 4; mf++)
                #pragma unroll
                for (int h = 0; h < 2; h++) {
                    int rc = m0w + mf * 16 + ar + h * 8;
                    sp[rc * 4 + (wid & 3)] = make_float2(rmax[mf][h], rsum[mf][h]);
                }
        }
        __syncthreads();
        if (tid < 128) {
            float m = -1e30f, s = 0.f;
            #pragma unroll
            for (int w = 0; w < 4; w++) {
                float2 p = sp[tid * 4 + w];
                float mm = fmaxf(m, p.x);
                s = s * fexp(m - mm) + p.y * fexp(p.x - mm);
                m = mm;
            }
            lse_part[(size_t)(m0 + tid) * NPART + blockIdx.y] = make_float2(m, s);
        }
    }
}

// ---------------- persistent LSTM ----------------
#define WPAD 1032
#define LP_SWH 0
#define LP_SWL 66048
#define LP_SHH 132096
#define LP_SHL 148608
#define LP_RED 165120
#define LP_GATES 173312
#define LP_BIAS 174336
#define LP_SMEM 174464

__global__ void __launch_bounds__(256)
lstm_persistent_kernel(const __nv_bfloat16* __restrict__ rwh,
                       const __nv_bfloat16* __restrict__ rwl,
                       const float* __restrict__ b_ih,
                       const float* __restrict__ b_hh)
{
    extern __shared__ char smraw[];
    __nv_bfloat16* swh = (__nv_bfloat16*)(smraw + LP_SWH);
    __nv_bfloat16* swl = (__nv_bfloat16*)(smraw + LP_SWL);
    __nv_bfloat16* shh = (__nv_bfloat16*)(smraw + LP_SHH);
    __nv_bfloat16* shl = (__nv_bfloat16*)(smraw + LP_SHL);
    float* red      = (float*)(smraw + LP_RED);
    float* sm_gates = (float*)(smraw + LP_GATES);
    float* sm_bias  = (float*)(smraw + LP_BIAS);

    int tid = threadIdx.x;
    int jb = blockIdx.x * 8;

    // one-time weight staging (hi+lo) + bias
    {
        uint32_t sb = (uint32_t)__cvta_generic_to_shared(smraw);
        #pragma unroll
        for (int i = 0; i < 32; i++) {
            int u = tid + 256 * i;
            int buf = u >> 12;
            int o = u & 4095;
            int row = o >> 7;
            int ch = o & 127;
            int g = row >> 3, jl = row & 7;
            const __nv_bfloat16* src = (buf ? rwl : rwh)
                + (size_t)(g * HID + jb + jl) * HID + ch * 8;
            cpasync16(sb + (uint32_t)(buf * LP_SWL + row * (WPAD * 2) + ch * 16), src);
        }
        CP_COMMIT();
        if (tid < 32) {
            int g = tid >> 3, jl = tid & 7;
            sm_bias[tid] = b_ih[g * HID + jb + jl] + b_hh[g * HID + jb + jl];
        }
        asm volatile("cp.async.wait_group 0;\n" ::: "memory");
        __syncthreads();
    }

    int wid = tid >> 5, lane = tid & 31;
    int ar = lane >> 2;
    int ac = (lane & 3) * 2;
    int ejl = tid >> 3, eb = tid & 7;
    float c_reg = 0.f;

    // transposed-xproj per-thread base pointer: row (tid>>3) of this CTA, batch (tid&7)
    const float* xpp;
    {
        int prow = tid >> 3, pb = tid & 7;
        int pg = prow >> 3, pjl = prow & 7;
        xpp = g_xproj + (size_t)(pg * HID + jb + pjl) * MM + pb;
    }

    for (int t = 0; t < TT; t++) {
        const float* hprev = g_hbuf[t & 1];
        float* hnext = g_hbuf[(t + 1) & 1];

        // prefetch xproj early (independent of h)
        float xp_pre = __ldcg(xpp + t * BB);

        // stage h: fp32 -> bf16 hi/lo smem
        {
            const float4* hp4 = (const float4*)hprev;
            #pragma unroll
            for (int i = 0; i < 8; i++) {
                int f4 = tid + 256 * i;
                float4 v = __ldcg(hp4 + f4);
                int batch = f4 >> 8;
                int k = (f4 & 255) * 4;
                int off = batch * WPAD + k;
                float h0 = __bfloat162float(__float2bfloat16(v.x));
                float h1 = __bfloat162float(__float2bfloat16(v.y));
                float h2 = __bfloat162float(__float2bfloat16(v.z));
                float h3 = __bfloat162float(__float2bfloat16(v.w));
                uint2 ph, pl;
                ph.x = pkbf(v.x, v.y);
                ph.y = pkbf(v.z, v.w);
                pl.x = pkbf(v.x - h0, v.y - h1);
                pl.y = pkbf(v.z - h2, v.w - h3);
                *(uint2*)(shh + off) = ph;
                *(uint2*)(shl + off) = pl;
            }
        }
        __syncthreads();

        // recurrent GEMM: warp wid handles k in [wid*128, wid*128+128)
        float acc[2][4];
        #pragma unroll
        for (int mt = 0; mt < 2; mt++)
            #pragma unroll
            for (int e = 0; e < 4; e++) acc[mt][e] = 0.f;

        #pragma unroll
        for (int ks8 = 0; ks8 < 8; ks8++) {
            int kk = wid * 128 + ks8 * 16;
            uint32_t bh[2], bl[2];
            bh[0] = *(const uint32_t*)(shh + ar * WPAD + kk + ac);
            bh[1] = *(const uint32_t*)(shh + ar * WPAD + kk + ac + 8);
            bl[0] = *(const uint32_t*)(shl + ar * WPAD + kk + ac);
            bl[1] = *(const uint32_t*)(shl + ar * WPAD + kk + ac + 8);
            #pragma unroll
            for (int mt = 0; mt < 2; mt++) {
                int r = mt * 16 + ar;
                uint32_t ah[4], al[4];
                ah[0] = *(const uint32_t*)(swh + r * WPAD + kk + ac);
                ah[1] = *(const uint32_t*)(swh + (r + 8) * WPAD + kk + ac);
                ah[2] = *(const uint32_t*)(swh + r * WPAD + kk + ac + 8);
                ah[3] = *(const uint32_t*)(swh + (r + 8) * WPAD + kk + ac + 8);
                al[0] = *(const uint32_t*)(swl + r * WPAD + kk + ac);
                al[1] = *(const uint32_t*)(swl + (r + 8) * WPAD + kk + ac);
                al[2] = *(const uint32_t*)(swl + r * WPAD + kk + ac + 8);
                al[3] = *(const uint32_t*)(swl + (r + 8) * WPAD + kk + ac + 8);
                mma16816(acc[mt], ah, bh);
                mma16816(acc[mt], ah, bl);
                mma16816(acc[mt], al, bh);
            }
        }

        // cross-warp k-reduce
        #pragma unroll
        for (int mt = 0; mt < 2; mt++)
            #pragma unroll
            for (int e = 0; e < 4; e++) {
                int row = mt * 16 + ar + ((e & 2) ? 8 : 0);
                int b = ac + (e & 1);
                red[row * 64 + b * 8 + wid] = acc[mt][e];
            }
        __syncthreads();

        {
            float4 p0 = *(float4*)(red + tid * 8);
            float4 p1 = *(float4*)(red + tid * 8 + 4);
            sm_gates[tid] = ((p0.x + p0.y) + (p0.z + p0.w))
                          + ((p1.x + p1.y) + (p1.z + p1.w))
                          + xp_pre + sm_bias[tid >> 3];
        }
        __syncthreads();

        if (tid < 64) {
            int j = jb + ejl;
            float gi = sm_gates[(0 * 8 + ejl) * 8 + eb];
            float gf = sm_gates[(1 * 8 + ejl) * 8 + eb];
            float gg = sm_gates[(2 * 8 + ejl) * 8 + eb];
            float go = sm_gates[(3 * 8 + ejl) * 8 + eb];
            gi = 1.f / (1.f + expf(-gi));
            gf = 1.f / (1.f + expf(-gf));
            gg = tanhf(gg);
            go = 1.f / (1.f + expf(-go));
            c_reg = gf * c_reg + gi * gg;
            float h = go * tanhf(c_reg);
            hnext[eb * HID + j] = h;
            size_t di = ((size_t)eb * TT + t) * HID + j;
            float hh = __bfloat162float(__float2bfloat16(h));
            g_hh2[di] = __float2bfloat16(h);
            g_hl2[di] = __float2bfloat16(h - hh);
            if (t == TT - 1) g_c[eb * HID + j] = c_reg;
        }

        // ---- flat all-poll grid barrier ----
        __syncthreads();
        __threadfence();
        if (tid == 0)
            *(volatile int*)&g_bar_flags[blockIdx.x * 32] = t + 1;
        if (wid == 0) {
            int idx = lane * 4;
            for (;;) {
                int ok = 1;
                #pragma unroll
                for (int q = 0; q < 4; q++)
                    ok &= (*(volatile int*)&g_bar_flags[(idx + q) * 32] >= t + 1);
                if (__all_sync(0xffffffffu, ok)) break;
            }
        }
        __syncthreads();
    }
}

// ---------------- LSE partial reduce + subtract ----------------
__global__ void __launch_bounds__(256)
lse_reduce_kernel(const float2* __restrict__ part)
{
    int row = blockIdx.x * 8 + (threadIdx.x >> 5);
    int lane = threadIdx.x & 31;
    float m = -1e30f, s = 0.f;
    for (int i = lane; i < NPART; i += 32) {
        float2 p = part[(size_t)row * NPART + i];
        float mm = fmaxf(m, p.x);
        s = s * fexp(m - mm) + p.y * fexp(p.x - mm);
        m = mm;
    }
    #pragma unroll
    for (int off = 16; off; off >>= 1) {
        float m2 = __shfl_xor_sync(0xffffffffu, m, off);
        float s2 = __shfl_xor_sync(0xffffffffu, s, off);
        float mm = fmaxf(m, m2);
        s = s * fexp(m - mm) + s2 * fexp(m2 - mm);
        m = mm;
    }
    if (lane == 0) g_lse[row] = m + logf(s);
}

__global__ void __launch_bounds__(256)
sub_lse_kernel(float* __restrict__ out)
{
    int row = blockIdx.x;
    float l = g_lse[row];
    float* p = out + (size_t)row * VOC;
    for (int i = threadIdx.x; i < VOC; i += 256) p[i] -= l;
}

__global__ void write_hidden_kernel(float* __restrict__ out)
{
    int i = blockIdx.x * blockDim.x + threadIdx.x;
    size_t base = (size_t)MM * VOC;
    if (i < BB * HID)               out[base + i] = g_hbuf[0][i];
    else if (i < 2 * BB * HID)      out[base + i] = g_c[i - BB * HID];
}

// ---------------- launcher ----------------
extern "C" void kernel_launch(void* const* d_in, const int* in_sizes, int n_in,
                              void* d_out, int out_size)
{
    const int*   x     = (const int*)  d_in[0];
    const float* emb_W = (const float*)d_in[1];
    const float* w_ih  = (const float*)d_in[2];
    const float* w_hh  = (const float*)d_in[3];
    const float* b_ih  = (const float*)d_in[4];
    const float* b_hh  = (const float*)d_in[5];
    const float* dec_b = (const float*)d_in[6];
    float* out = (float*)d_out;

    float* xproj_p; cudaGetSymbolAddress((void**)&xproj_p, g_xproj);
    float2* lsepart_p; cudaGetSymbolAddress((void**)&lsepart_p, g_lsepart);
    __nv_bfloat16 *ebh, *ebl, *wh, *wl, *rwh, *rwl, *xh, *xl, *hh2, *hl2;
    cudaGetSymbolAddress((void**)&ebh, g_ebh);
    cudaGetSymbolAddress((void**)&ebl, g_ebl);
    cudaGetSymbolAddress((void**)&wh,  g_wh);
    cudaGetSymbolAddress((void**)&wl,  g_wl);
    cudaGetSymbolAddress((void**)&rwh, g_rwh);
    cudaGetSymbolAddress((void**)&rwl, g_rwl);
    cudaGetSymbolAddress((void**)&xh,  g_xh);
    cudaGetSymbolAddress((void**)&xl,  g_xl);
    cudaGetSymbolAddress((void**)&hh2, g_hh2);
    cudaGetSymbolAddress((void**)&hl2, g_hl2);

    cudaFuncSetAttribute(lstm_persistent_kernel,
                         cudaFuncAttributeMaxDynamicSharedMemorySize, LP_SMEM);
    cudaFuncSetAttribute(mm_bf16_kernel,
                         cudaFuncAttributeMaxDynamicSharedMemorySize, MMSMEM);

    zero_state_kernel<<<(BB * HID + 255) / 256, 256>>>();

    gather_kernel<<<MM, 128>>>(x, emb_W, xh, xl);

    split_kernel<<<4096, 256>>>(emb_W, ebh, ebl, (long)VOC * HID / 8);
    split_kernel<<<512,  256>>>(w_ih,  wh,  wl,  (long)GATES * HID / 8);
    split_kernel<<<512,  256>>>(w_hh,  rwh, rwl, (long)GATES * HID / 8);

    // x_proj TRANSPOSED: C[gate][m] = w_ih @ emb^T (bias folded into LSTM)
    {
        dim3 grid(GATES / 128, MM / 128);    // 32 x 16
        mm_bf16_kernel<<<grid, 256, MMSMEM>>>(wh, wl, xh, xl,
                                              (const float*)0, (const float*)0,
                                              xproj_p, MM, MM, HID, (float2*)0);
    }

    lstm_persistent_kernel<<<HID / 8, 256, LP_SMEM>>>(rwh, rwl, b_ih, b_hh);

    // decoder: logits = h_all @ emb_W^T + dec_b, with fused LSE partials
    {
        dim3 grid(MM / 128, NPART);          // 16 x 393
        mm_bf16_kernel<<<grid, 256, MMSMEM>>>(hh2, hl2, ebh, ebl, dec_b,
                                              (const float*)0, out, VOC, VOC, HID,
                                              lsepart_p);
    }

    lse_reduce_kernel<<<MM / 8, 256>>>(lsepart_p);
    sub_lse_kernel<<<MM, 256>>>(out);

    if (out_size >= MM * VOC + 2 * BB * HID)
        write_hidden_kernel<<<(2 * BB * HID + 255) / 256, 256>>>(out);
}